// round 13
// baseline (speedup 1.0000x reference)
#include <cuda_runtime.h>

// Problem constants
#define BB 4
#define DDIM 64
#define HW (512*512)
#define KK 32

// Accum tiling: each tile = 2 channels (one pair) x CP pixels of one image.
#define T 256
#define CP 16384
#define NCHUNK (HW/CP)     // 16
#define NB 8               // batches of 2 float4-groups (8 pixels) per thread
#define NQ (DDIM/2)        // 32 channel pairs
#define NTILE (NCHUNK*NQ*BB)   // 2048 accum tiles
#define NCTILE (64*BB)         // 256 count tiles

// Global scratch (no allocations; fully overwritten each call -> no zeroing)
__device__ float g_sum_part[BB*NQ*KK*2*NCHUNK];  // [(b,q,k)][ch][chunk]
__device__ float g_sq_part[BB*KK*NQ*NCHUNK];     // [(b,k)][q][chunk]
__device__ float g_cnt_part[BB*KK*64];           // [(b,k)][chunk64]
__device__ unsigned char g_lab8[BB*HW];          // packed labels (bytes)
__device__ float g_loss[BB];                     // per-image losses

// Device-wide sense-reversal barriers (cnt returns to 0 after each use;
// gen monotonically increases across graph replays -> replay-safe).
__device__ unsigned g_bar_cnt[4];
__device__ unsigned g_bar_gen[4];

__device__ __forceinline__ void grid_barrier(int i, unsigned nb) {
    __syncthreads();
    if (threadIdx.x == 0) {
        __threadfence();
        unsigned gen = atomicAdd(&g_bar_gen[i], 0u);      // snapshot before arrive
        if (atomicAdd(&g_bar_cnt[i], 1u) == nb - 1u) {
            g_bar_cnt[i] = 0u;
            __threadfence();
            atomicAdd(&g_bar_gen[i], 1u);
        } else {
            while (atomicAdd(&g_bar_gen[i], 0u) == gen) __nanosleep(64);
        }
        __threadfence();
    }
    __syncthreads();
}

__global__ __launch_bounds__(T, 2) void fused_kernel(
    const float* __restrict__ feats, const int* __restrict__ labels,
    float* __restrict__ out, unsigned nb)
{
    extern __shared__ float smem[];
    const int t = threadIdx.x, lane = t & 31, w = t >> 5;
    const unsigned bid = blockIdx.x;

    // ---------------- Phase A: label histogram + byte-pack ----------------
    {
        float* s_cnt = smem;                    // KK*T floats
        for (unsigned tile = bid; tile < NCTILE; tile += nb) {
            const int chunk64 = tile & 63;
            const int b = tile >> 6;
            for (int i = t; i < KK*T; i += T) s_cnt[i] = 0.f;
            __syncthreads();
            const int4* L4 = (const int4*)(labels + (size_t)b * HW + (size_t)chunk64 * 4096);
            uchar4* P4 = (uchar4*)g_lab8 + ((size_t)b * HW >> 2) + (size_t)chunk64 * 1024;
#pragma unroll
            for (int g = 0; g < 4; ++g) {
                int4 L = L4[g*T + t];
                int x = L.x & 31, y = L.y & 31, z = L.z & 31, u = L.w & 31;
                s_cnt[x*T + t] += 1.f;
                s_cnt[y*T + t] += 1.f;
                s_cnt[z*T + t] += 1.f;
                s_cnt[u*T + t] += 1.f;
                P4[g*T + t] = make_uchar4((unsigned char)x, (unsigned char)y,
                                          (unsigned char)z, (unsigned char)u);
            }
            __syncthreads();
#pragma unroll
            for (int bbn = 0; bbn < 4; ++bbn) {
                const int bin = w*4 + bbn;
                float c = 0.f;
#pragma unroll
                for (int j = 0; j < T/32; ++j) c += s_cnt[bin*T + j*32 + lane];
#pragma unroll
                for (int off = 16; off; off >>= 1) c += __shfl_xor_sync(0xffffffffu, c, off);
                if (lane == 0) g_cnt_part[(b*KK + bin)*64 + chunk64] = c;
            }
            __syncthreads();
        }
    }
    grid_barrier(0, nb);

    // ---------------- Phase B: feature accumulation ----------------
    {
        float2* s2   = (float2*)smem;           // KK*T float2
        float*  s_sq = smem + KK*T*2;           // KK*T floats

        for (unsigned tile = bid; tile < NTILE; tile += nb) {
            const int chunk = tile & (NCHUNK-1);
            const int q     = (tile >> 4) & (NQ-1);
            const int b     = tile >> 9;

            for (int i = t; i < KK*T; i += T) { s2[i] = make_float2(0.f, 0.f); s_sq[i] = 0.f; }
            __syncthreads();

            const size_t base = (size_t)(b*DDIM + q*2) * HW + (size_t)chunk * CP;
            const float4* __restrict__ F0 = (const float4*)(feats + base);
            const float4* __restrict__ F1 = (const float4*)(feats + base + HW);
            const uchar4* __restrict__ LB = (const uchar4*)g_lab8
                                          + (((size_t)b * HW + (size_t)chunk * CP) >> 2);

            // Triple-buffered staging: prefetch distance 2 batches (~1200 cyc cover).
            float4 c[3][2][2];
            uchar4 lb[3][2];

#pragma unroll
            for (int bt = 0; bt < 2; ++bt)
#pragma unroll
                for (int g = 0; g < 2; ++g) {
                    const int idx = (bt*2 + g)*T + t;
                    lb[bt][g] = LB[idx];
                    c[bt][g][0] = F0[idx]; c[bt][g][1] = F1[idx];
                }

#pragma unroll
            for (int bt = 0; bt < NB; ++bt) {
                const int cur = bt % 3;
                if (bt + 2 < NB) {
                    const int pf = (bt + 2) % 3;
#pragma unroll
                    for (int g = 0; g < 2; ++g) {
                        const int idx = ((bt+2)*2 + g)*T + t;
                        lb[pf][g] = LB[idx];
                        c[pf][g][0] = F0[idx]; c[pf][g][1] = F1[idx];
                    }
                }
#pragma unroll
                for (int g = 0; g < 2; ++g) {
                    const float4 v0 = c[cur][g][0], v1 = c[cur][g][1];
                    const uchar4 L  = lb[cur][g];
#pragma unroll
                    for (int p = 0; p < 4; ++p) {
                        const float x = (p==0)?v0.x:(p==1)?v0.y:(p==2)?v0.z:v0.w;
                        const float y = (p==0)?v1.x:(p==1)?v1.y:(p==2)?v1.z:v1.w;
                        const int bin = (p==0)?L.x:(p==1)?L.y:(p==2)?L.z:L.w;
                        const int col = bin*T + t;
                        float2 a = s2[col];
                        a.x += x; a.y += y;
                        s2[col] = a;
                        s_sq[col] = fmaf(x, x, fmaf(y, y, s_sq[col]));
                    }
                }
            }
            __syncthreads();

            // flush: warp w reduces bins 4w..4w+3; non-atomic partial writes
#pragma unroll
            for (int bbn = 0; bbn < 4; ++bbn) {
                const int bin = w*4 + bbn;
                float ax = 0.f, ay = 0.f, sq = 0.f;
#pragma unroll
                for (int j = 0; j < T/32; ++j) {
                    const int col = bin*T + j*32 + lane;
                    float2 v = s2[col];
                    ax += v.x; ay += v.y;
                    sq += s_sq[col];
                }
#pragma unroll
                for (int off = 16; off; off >>= 1) {
                    ax += __shfl_xor_sync(0xffffffffu, ax, off);
                    ay += __shfl_xor_sync(0xffffffffu, ay, off);
                    sq += __shfl_xor_sync(0xffffffffu, sq, off);
                }
                if (lane == 0) {
                    const int sbase = ((b*NQ + q)*KK + bin)*(2*NCHUNK);
                    g_sum_part[sbase + chunk]          = ax;
                    g_sum_part[sbase + NCHUNK + chunk] = ay;
                    g_sq_part[((b*KK + bin)*NQ + q)*NCHUNK + chunk] = sq;
                }
            }
            __syncthreads();
        }
    }
    grid_barrier(1, nb);

    // ---------------- Phase C: per-image finalize (blocks 0..BB-1) ----------------
    if (bid < BB) {
        const int b = bid;
        float* s_mean = smem;                   // KK*65 floats (padded rows)
        float* s_cnt  = smem + KK*65;           // KK
        float* s_acc  = s_cnt + KK;             // 3: var, hinge, reg

        if (t < 3) s_acc[t] = 0.f;

        // counts: warp w reduces bins 4w..4w+3 (64 chunk-partials each)
#pragma unroll
        for (int bbn = 0; bbn < 4; ++bbn) {
            const int bin = w*4 + bbn;
            const float* p = &g_cnt_part[(b*KK + bin)*64];
            float cc = p[lane] + p[lane + 32];
#pragma unroll
            for (int off = 16; off; off >>= 1) cc += __shfl_xor_sync(0xffffffffu, cc, off);
            if (lane == 0) s_cnt[bin] = cc;
        }
        __syncthreads();

        // means: 2048 (k,d) entries, 8 per thread, 16 chunk-partials each
        for (int i = t; i < KK*DDIM; i += T) {
            const int k = i >> 6, d = i & 63, q = d >> 1, ch = d & 1;
            const float4* p4 = (const float4*)&g_sum_part[((b*NQ + q)*KK + k)*(2*NCHUNK) + ch*NCHUNK];
            float4 a = p4[0], b4 = p4[1], c4 = p4[2], d4 = p4[3];
            float s = ((a.x + a.y) + (a.z + a.w)) + ((b4.x + b4.y) + (b4.z + b4.w))
                    + ((c4.x + c4.y) + (c4.z + c4.w)) + ((d4.x + d4.y) + (d4.z + d4.w));
            s_mean[k*65 + d] = s / fmaxf(s_cnt[k], 1.f);
        }
        __syncthreads();

        // per-cluster m2 + sumsq: warp w handles bins w, w+8, w+16, w+24
#pragma unroll
        for (int rep = 0; rep < 4; ++rep) {
            const int bin = w + rep*8;
            float m0 = s_mean[bin*65 + lane];
            float m1 = s_mean[bin*65 + lane + 32];
            float p = fmaf(m0, m0, m1*m1);
            const float4* q4 = (const float4*)&g_sq_part[(b*KK + bin)*NQ*NCHUNK]; // 512 floats
            float sq = 0.f;
#pragma unroll
            for (int j = 0; j < 4; ++j) {
                float4 v = q4[lane + 32*j];
                sq += (v.x + v.y) + (v.z + v.w);
            }
#pragma unroll
            for (int off = 16; off; off >>= 1) {
                p  += __shfl_xor_sync(0xffffffffu, p,  off);
                sq += __shfl_xor_sync(0xffffffffu, sq, off);
            }
            if (lane == 0) {
                float cc = s_cnt[bin];
                if (cc > 0.f) {
                    // sum ||f - mu||^2 = sumsq - cnt*||mu||^2 ; var_per = that / cnt
                    atomicAdd(&s_acc[0], (sq - cc*p) / cc);
                    atomicAdd(&s_acc[2], sqrtf(p));
                }
            }
        }

        // pairwise hinge: 4 (i,j) cells per thread
        for (int p = t; p < KK*KK; p += T) {
            const int i = p >> 5, j = p & 31;
            if (j > i && s_cnt[i] > 0.f && s_cnt[j] > 0.f) {
                float dsq = 0.f;
#pragma unroll
                for (int d = 0; d < DDIM; ++d) {
                    float df = s_mean[i*65 + d] - s_mean[j*65 + d];
                    dsq = fmaf(df, df, dsq);
                }
                float dist = sqrtf(dsq);
                if (dist < 3.0f) {            // 2*delta_d, delta_d = 1.5
                    float h = 3.0f - dist;
                    atomicAdd(&s_acc[1], h*h);
                }
            }
        }
        __syncthreads();

        if (t == 0) {
            float ncl = 0.f;
            for (int k = 0; k < KK; ++k) ncl += (s_cnt[k] > 0.f) ? 1.f : 0.f;
            float dist_loss = s_acc[1] / fmaxf(ncl - 1.f, 1.f);
            g_loss[b] = (s_acc[0] + dist_loss + 0.001f * s_acc[2]) / fmaxf(ncl, 1.f);
        }
    }
    grid_barrier(2, nb);

    // ---------------- Phase D: combine ----------------
    if (bid == 0 && t == 0)
        out[0] = (g_loss[0] + g_loss[1] + g_loss[2] + g_loss[3]) / (float)(BB + 1);
}

extern "C" void kernel_launch(void* const* d_in, const int* in_sizes, int n_in,
                              void* d_out, int out_size) {
    const float* feats  = (const float*)d_in[0];
    const int*   labels = (const int*)d_in[1];
    float*       out    = (float*)d_out;

    const int smem_bytes = KK*T*3*(int)sizeof(float);   // 98304 -> 2 blocks/SM
    cudaFuncSetAttribute(fused_kernel, cudaFuncAttributeMaxDynamicSharedMemorySize,
                         smem_bytes);

    int dev = 0, sms = 148, occ = 0;
    cudaGetDevice(&dev);
    cudaDeviceGetAttribute(&sms, cudaDevAttrMultiProcessorCount, dev);
    cudaOccupancyMaxActiveBlocksPerMultiprocessor(&occ, fused_kernel, T, smem_bytes);
    if (occ < 1) occ = 1;
    unsigned nb = (unsigned)(sms * occ);
    if (nb > NTILE) nb = NTILE;

    fused_kernel<<<nb, T, smem_bytes>>>(feats, labels, out, nb);
}